// round 5
// baseline (speedup 1.0000x reference)
#include <cuda_runtime.h>
#include <stdint.h>

typedef unsigned long long u64;

// Fixed problem envelope: 2E = 1,600,000 (E=800,000), n = 50,000 (< 65536 so
// block-row/col ids fit 16 bits each of the 64-bit sort key).
#define E_MAX   850000
#define N_MAX   65536
#define ENT_MAX (N_MAX + 2*E_MAX)

__device__ float g_triu[(size_t)E_MAX * 16];   // LᵀR per first-half edge
__device__ float g_diag[(size_t)N_MAX * 16];   // per-node accumulated MᵀM
__device__ u64   g_entries[ENT_MAX];           // (r<<48)|(c<<32)|id
__device__ int   g_cnt[N_MAX];
__device__ int   g_fill[N_MAX];
__device__ int   g_rowstart[N_MAX + 1];
__device__ int   g_part[512];

// ---------------------------------------------------------------- init
__global__ void k_init(int n, int total) {
    int t = blockIdx.x * blockDim.x + threadIdx.x;
    if (t < n * 16) g_diag[t] = 0.0f;
    if (t < n) { g_cnt[t] = 1; g_fill[t] = 0; }   // +1 for the diag entry
    if (t == 0) g_rowstart[n] = total;
}

// ------------------------------------------------- per-edge 4x4 products
// For e in [0,E): load L = maps[e], R = maps[E+e].
//   diag[ei0[e]]   += LᵀL     diag[ei0[E+e]] += RᵀR
//   triu[e]         = LᵀR
//   cnt[row]++, cnt[col]++   (row = ei0[e], col = ei1[e])
__global__ void __launch_bounds__(256) k_edges(
    const float* __restrict__ maps, const int* __restrict__ ei,
    int E, int twoE) {
    int e = blockIdx.x * blockDim.x + threadIdx.x;
    if (e >= E) return;

    float L[4][4], R[4][4];
    const float4* Lp = reinterpret_cast<const float4*>(maps) + e * 4;
    const float4* Rp = reinterpret_cast<const float4*>(maps) + (E + e) * 4;
#pragma unroll
    for (int a = 0; a < 4; a++) {
        float4 q = Lp[a];
        L[a][0] = q.x; L[a][1] = q.y; L[a][2] = q.z; L[a][3] = q.w;
        float4 p = Rp[a];
        R[a][0] = p.x; R[a][1] = p.y; R[a][2] = p.z; R[a][3] = p.w;
    }
    int nodeL = ei[e];          // == row for this edge
    int nodeR = ei[E + e];
    int col   = ei[twoE + e];

    float* dl = g_diag + (size_t)nodeL * 16;
    float* dr = g_diag + (size_t)nodeR * 16;
#pragma unroll
    for (int b = 0; b < 4; b++)
#pragma unroll
        for (int c = 0; c < 4; c++) {
            float s = L[0][b]*L[0][c] + L[1][b]*L[1][c] + L[2][b]*L[2][c] + L[3][b]*L[3][c];
            atomicAdd(dl + b * 4 + c, s);
            float t = R[0][b]*R[0][c] + R[1][b]*R[1][c] + R[2][b]*R[2][c] + R[3][b]*R[3][c];
            atomicAdd(dr + b * 4 + c, t);
        }

    float4* Tp = reinterpret_cast<float4*>(g_triu) + e * 4;
#pragma unroll
    for (int x = 0; x < 4; x++) {
        float4 t;
        t.x = L[0][x]*R[0][0] + L[1][x]*R[1][0] + L[2][x]*R[2][0] + L[3][x]*R[3][0];
        t.y = L[0][x]*R[0][1] + L[1][x]*R[1][1] + L[2][x]*R[2][1] + L[3][x]*R[3][1];
        t.z = L[0][x]*R[0][2] + L[1][x]*R[1][2] + L[2][x]*R[2][2] + L[3][x]*R[3][2];
        t.w = L[0][x]*R[0][3] + L[1][x]*R[1][3] + L[2][x]*R[2][3] + L[3][x]*R[3][3];
        Tp[x] = t;
    }

    atomicAdd(&g_cnt[nodeL], 1);
    atomicAdd(&g_cnt[col], 1);
}

// ------------------------------------------------- exclusive scan (3 kernels)
__global__ void k_scan1(int n) {
    __shared__ int sh[256];
    int i = blockIdx.x * 256 + threadIdx.x;
    sh[threadIdx.x] = (i < n) ? g_cnt[i] : 0;
    __syncthreads();
#pragma unroll
    for (int s = 128; s > 0; s >>= 1) {
        if (threadIdx.x < s) sh[threadIdx.x] += sh[threadIdx.x + s];
        __syncthreads();
    }
    if (threadIdx.x == 0) g_part[blockIdx.x] = sh[0];
}

__global__ void k_scan2(int nblk) {   // 1 block, nblk <= 256
    __shared__ int sh[256];
    int v = (threadIdx.x < nblk) ? g_part[threadIdx.x] : 0;
    sh[threadIdx.x] = v;
    __syncthreads();
    for (int off = 1; off < 256; off <<= 1) {
        int t = (threadIdx.x >= off) ? sh[threadIdx.x - off] : 0;
        __syncthreads();
        sh[threadIdx.x] += t;
        __syncthreads();
    }
    if (threadIdx.x < nblk) g_part[threadIdx.x] = sh[threadIdx.x] - v;  // exclusive
}

__global__ void k_scan3(int n) {
    __shared__ int sh[256];
    int i = blockIdx.x * 256 + threadIdx.x;
    int v = (i < n) ? g_cnt[i] : 0;
    sh[threadIdx.x] = v;
    __syncthreads();
    for (int off = 1; off < 256; off <<= 1) {
        int t = (threadIdx.x >= off) ? sh[threadIdx.x - off] : 0;
        __syncthreads();
        sh[threadIdx.x] += t;
        __syncthreads();
    }
    if (i < n) g_rowstart[i] = g_part[blockIdx.x] + sh[threadIdx.x] - v;
}

// ------------------------------------------------- bucket fill (unordered)
// id encodes stable source rank: diag r -> r, ij e -> n+e, ji e -> n+E+e.
__global__ void k_fill(const int* __restrict__ ei, int n, int E, int twoE) {
    int t = blockIdx.x * blockDim.x + threadIdx.x;
    if (t < n) {
        u64 key = ((u64)t << 48) | ((u64)t << 32) | (unsigned)t;
        int pos = g_rowstart[t] + atomicAdd(&g_fill[t], 1);
        g_entries[pos] = key;
    } else if (t < n + E) {
        int e = t - n;
        int row = ei[e], col = ei[twoE + e];
        u64 kij = ((u64)row << 48) | ((u64)col << 32) | (unsigned)(n + e);
        int p1 = g_rowstart[row] + atomicAdd(&g_fill[row], 1);
        g_entries[p1] = kij;
        u64 kji = ((u64)col << 48) | ((u64)row << 32) | (unsigned)(n + E + e);
        int p2 = g_rowstart[col] + atomicAdd(&g_fill[col], 1);
        g_entries[p2] = kji;
    }
}

// ------------------------------------------------- per-bucket sort
// One warp per block-row; bitonic in shared for L<=128 (expected max ~70),
// global odd-even transposition fallback otherwise.
__global__ void __launch_bounds__(256) k_sort(int n) {
    __shared__ u64 sb[8][128];
    int w = threadIdx.x >> 5, lane = threadIdx.x & 31;
    int r = blockIdx.x * 8 + w;
    if (r >= n) return;
    int rs = g_rowstart[r], re = g_rowstart[r + 1];
    int L = re - rs;
    if (L <= 1) return;

    if (L <= 128) {
        int P = 2;
        while (P < L) P <<= 1;
        for (int i = lane; i < P; i += 32)
            sb[w][i] = (i < L) ? g_entries[rs + i] : ~0ULL;
        __syncwarp();
        for (int k = 2; k <= P; k <<= 1) {
            for (int j = k >> 1; j > 0; j >>= 1) {
                for (int i = lane; i < P; i += 32) {
                    int x = i ^ j;
                    if (x > i) {
                        u64 A = sb[w][i], B = sb[w][x];
                        bool up = ((i & k) == 0);
                        if ((A > B) == up) { sb[w][i] = B; sb[w][x] = A; }
                    }
                }
                __syncwarp();
            }
        }
        for (int i = lane; i < L; i += 32) g_entries[rs + i] = sb[w][i];
    } else {
        for (int round = 0; round < L; round++) {
            for (int idx = rs + (round & 1) + 2 * lane; idx + 1 < re; idx += 64) {
                u64 A = g_entries[idx], B = g_entries[idx + 1];
                if (A > B) { g_entries[idx] = B; g_entries[idx + 1] = A; }
            }
            __syncwarp();
        }
    }
}

// ------------------------------------------------- emit sorted COO
__global__ void __launch_bounds__(256) k_write(
    float* __restrict__ out_i, float* __restrict__ out_j,
    float* __restrict__ out_v, int n, int E, int total) {
    int p = blockIdx.x * blockDim.x + threadIdx.x;
    if (p >= total) return;
    u64 key = g_entries[p];
    int r = (int)(key >> 48);
    int c = (int)((key >> 32) & 0xFFFF);
    unsigned id = (unsigned)(key & 0xFFFFFFFFu);
    int rs = g_rowstart[r], re = g_rowstart[r + 1];
    int cnt = re - rs;

    // tie group over identical (r,c) — expected size 1
    u64 hi = key >> 32;
    int gs = p;
    while (gs > rs && (g_entries[gs - 1] >> 32) == hi) gs--;
    int ge = p + 1;
    while (ge < re && (g_entries[ge] >> 32) == hi) ge++;
    int eq = ge - gs, rk = p - gs;

    float v[4][4];
    if (id < (unsigned)n) {
        const float4* dp = reinterpret_cast<const float4*>(g_diag) + (size_t)id * 4;
#pragma unroll
        for (int a = 0; a < 4; a++) {
            float4 q = dp[a];
            v[a][0] = q.x; v[a][1] = q.y; v[a][2] = q.z; v[a][3] = q.w;
        }
    } else if (id < (unsigned)(n + E)) {
        const float4* tp = reinterpret_cast<const float4*>(g_triu) + (size_t)(id - n) * 4;
#pragma unroll
        for (int a = 0; a < 4; a++) {
            float4 q = tp[a];
            v[a][0] = -q.x; v[a][1] = -q.y; v[a][2] = -q.z; v[a][3] = -q.w;
        }
    } else {
        const float4* tp = reinterpret_cast<const float4*>(g_triu) + (size_t)(id - n - E) * 4;
#pragma unroll
        for (int b = 0; b < 4; b++) {      // transposed: v[a][b] = -T[b][a]
            float4 q = tp[b];
            v[0][b] = -q.x; v[1][b] = -q.y; v[2][b] = -q.z; v[3][b] = -q.w;
        }
    }

    int base = 16 * rs + 4 * (gs - rs);
    float fj0 = (float)(c * 4);
    if (eq == 1) {
#pragma unroll
        for (int a = 0; a < 4; a++) {
            int pos = base + a * 4 * cnt;
            float fi = (float)(r * 4 + a);
            *reinterpret_cast<float4*>(out_i + pos) = make_float4(fi, fi, fi, fi);
            *reinterpret_cast<float4*>(out_j + pos) =
                make_float4(fj0, fj0 + 1.0f, fj0 + 2.0f, fj0 + 3.0f);
            *reinterpret_cast<float4*>(out_v + pos) =
                make_float4(v[a][0], v[a][1], v[a][2], v[a][3]);
        }
    } else {
#pragma unroll
        for (int a = 0; a < 4; a++)
#pragma unroll
            for (int b = 0; b < 4; b++) {
                int pos = base + a * 4 * cnt + b * eq + rk;
                out_i[pos] = (float)(r * 4 + a);
                out_j[pos] = fj0 + (float)b;
                out_v[pos] = v[a][b];
            }
    }
}

// ---------------------------------------------------------------- launch
extern "C" void kernel_launch(void* const* d_in, const int* in_sizes, int n_in,
                              void* d_out, int out_size) {
    const float* maps = (const float*)d_in[0];
    const int*   ei   = (const int*)d_in[1];

    int twoE = in_sizes[0] / 16;        // 1,600,000
    int E    = twoE / 2;                // 800,000
    // out = [idx0 | idx1 | vals], each 16*(n+2E) fp32  =>  n = out/48 - 2E
    int n     = out_size / 48 - twoE;   // 50,000
    int total = n + twoE;               // block entries
    int nnz   = 16 * total;
    float* out = (float*)d_out;

    int nblk_scan = (n + 255) / 256;

    k_init <<<(n * 16 + 255) / 256, 256>>>(n, total);
    k_edges<<<(E + 255) / 256, 256>>>(maps, ei, E, twoE);
    k_scan1<<<nblk_scan, 256>>>(n);
    k_scan2<<<1, 256>>>(nblk_scan);
    k_scan3<<<nblk_scan, 256>>>(n);
    k_fill <<<(n + E + 255) / 256, 256>>>(ei, n, E, twoE);
    k_sort <<<(n + 7) / 8, 256>>>(n);
    k_write<<<(total + 255) / 256, 256>>>(out, out + nnz, out + 2 * nnz, n, E, total);
}